// round 1
// baseline (speedup 1.0000x reference)
#include <cuda_runtime.h>
#include <math.h>

#define NF     40
#define NG     4
#define GF     10
#define TT     64000
#define NBATCH 32
#define NP     400
#define KMAXA  456   // array bound for taps (k <= 451, rounded to 4 -> 452)
#define KRMAX  452
#define WSMAX  404
#define XSLEN  864   // max input window span = (ws-1)*cs + kR <= 854

// ---- per-launch-computed meta + filter weights (zero-initialized .bss) ----
__device__ int   d_cs[NG], d_ps[NG], d_k[NG], d_kR[NG], d_ws[NG], d_L[NG];
__device__ float d_cosk[NG][GF][KMAXA];   // tail beyond k stays 0 forever
__device__ float d_sink[NG][GF][KMAXA];
__device__ float d_win [NG][GF][WSMAX];

// ============================================================================
// Setup: replicate the host-side meta computation + Gabor/pool weight tables.
// One block; deterministic; idempotent across graph replays.
// ============================================================================
__global__ void setup_kernel(const float* __restrict__ cf,
                             const float* __restrict__ bw,
                             const float* __restrict__ pw) {
    __shared__ int s_cs[NG], s_k[NG], s_ws[NG];
    const int tid = threadIdx.x;

    const double Zd   = sqrt(2.0 * log(2.0)) / M_PI;
    const float bwlo  = (float)(2.0   * Zd);
    const float bwhi  = (float)(401.0 * Zd);
    const float pi_f  = (float)M_PI;

    if (tid < NG) {
        const int g = tid;
        float cfm = 0.f, bwm = 0.f;
        for (int f = 0; f < GF; f++) {
            float c = fminf(fmaxf(cf[g * GF + f], 0.f), pi_f);
            float b = fminf(fmaxf(bw[g * GF + f], bwlo), bwhi);
            cfm = fmaxf(cfm, c);
            bwm = fmaxf(bwm, b);
        }
        double s = M_PI / (double)cfm;
        if (s < 1.0) s = 1.0;
        const int divs[12] = {160, 80, 40, 32, 20, 16, 10, 8, 5, 4, 2, 1};
        int cs = 1;
        for (int i = 0; i < 12; i++) {
            if ((double)divs[i] <= s) { cs = divs[i]; break; }
        }
        int k = (int)((double)bwm * 3.0);
        if ((k & 1) == 0) k += 1;
        int ws = (int)(401.0 / (double)cs + 0.5);
        if ((ws & 1) == 0) ws += 1;

        d_cs[g] = cs;
        d_ps[g] = 160 / cs;
        d_k[g]  = k;
        d_kR[g] = (k + 3) & ~3;
        d_ws[g] = ws;
        d_L[g]  = (TT - 1) / cs + 1;
        s_cs[g] = cs; s_k[g] = k; s_ws[g] = ws;
    }
    __syncthreads();

    for (int g = 0; g < NG; g++) {
        const int k  = s_k[g];
        const int ws = s_ws[g];
        const int cs = s_cs[g];
        const int kh = k >> 1;

        // Gabor kernels: norm * {cos,sin}(t*cf) * exp(-t^2/(2 bw^2))
        for (int idx = tid; idx < k * GF; idx += blockDim.x) {
            const int f  = idx / k;
            const int dw = idx - f * k;
            const int gi = g * GF + f;
            const float cfc = fminf(fmaxf(cf[gi], 0.f), pi_f);
            const float bwc = fminf(fmaxf(bw[gi], bwlo), bwhi);
            const double t  = (double)(dw - kh);
            const double bd = (double)bwc;
            const double gauss = exp(-(t * t) / (2.0 * bd * bd));
            const double norm  = 1.0 / (sqrt(2.0 * M_PI) * bd);
            double sn, csn;
            sincos(t * (double)cfc, &sn, &csn);
            d_cosk[g][f][dw] = (float)(norm * csn * gauss);
            d_sink[g][f][dw] = (float)(norm * sn  * gauss);
        }

        // Gaussian pooling windows
        for (int idx = tid; idx < ws * GF; idx += blockDim.x) {
            const int f = idx / ws;
            const int w = idx - f * ws;
            const int gi = g * GF + f;
            const float pwc = fminf(fmaxf(pw[gi], (float)(2.0 / 401.0)), 0.5f);
            const double sigma = (double)pwc / (double)cs * 401.0 / (double)ws;
            const double c = 0.5 * (double)(ws - 1);
            const double u = ((double)w - c) / (sigma * c);
            d_win[g][f][w] = (float)exp(-0.5 * u * u);
        }
    }
}

// ============================================================================
// Main fused kernel: one block per (pool position p, batch b, group g).
// 10 warps, one filter each. Lanes stride over pooling-window positions.
// ============================================================================
__global__ __launch_bounds__(320) void leaf_kernel(const float* __restrict__ x,
                                                   float* __restrict__ out) {
    const int g = blockIdx.z;
    const int b = blockIdx.y;
    const int p = blockIdx.x;

    const int cs  = d_cs[g];
    const int ps  = d_ps[g];
    const int ws  = d_ws[g];
    const int kR  = d_kR[g];
    const int L   = d_L[g];
    const int wsh = ws >> 1;
    const int kh  = d_k[g] >> 1;

    extern __shared__ float smem[];
    float* xs  = smem;                 // [XSLEN]
    float* cks = smem + XSLEN;         // [GF*kR]
    float* sks = cks + GF * kR;        // [GF*kR]

    const int tid = threadIdx.x;
    const int jbase = p * ps - wsh;
    const int base  = jbase * cs - kh;
    const float* xb = x + b * TT;

    // Stage input window (zero-padded); fill the full XSLEN so float4-rounded
    // tap reads never touch garbage.
    for (int i = tid; i < XSLEN; i += 320) {
        const int idx = base + i;
        xs[i] = ((unsigned)idx < (unsigned)TT) ? xb[idx] : 0.f;
    }
    // Stage this group's Gabor kernels (tail taps are 0 in global).
    for (int i = tid; i < GF * kR; i += 320) {
        const int f  = i / kR;
        const int dw = i - f * kR;
        cks[i] = d_cosk[g][f][dw];
        sks[i] = d_sink[g][f][dw];
    }
    __syncthreads();

    const int warp = tid >> 5;
    const int lane = tid & 31;
    const int f = warp;
    const float* ckf = cks + f * kR;
    const float* skf = sks + f * kR;
    const float* wnf = d_win[g][f];

    float acc = 0.f;
    for (int w = lane; w < ws; w += 32) {
        const int j = jbase + w;
        if ((unsigned)j < (unsigned)L) {
            const float* xw = xs + w * cs;
            float C = 0.f, S = 0.f;
            for (int dw = 0; dw < kR; dw += 4) {
                const float4 c4 = *reinterpret_cast<const float4*>(ckf + dw);
                const float4 s4 = *reinterpret_cast<const float4*>(skf + dw);
                const float x0 = xw[dw + 0];
                const float x1 = xw[dw + 1];
                const float x2 = xw[dw + 2];
                const float x3 = xw[dw + 3];
                C = fmaf(c4.x, x0, C); C = fmaf(c4.y, x1, C);
                C = fmaf(c4.z, x2, C); C = fmaf(c4.w, x3, C);
                S = fmaf(s4.x, x0, S); S = fmaf(s4.y, x1, S);
                S = fmaf(s4.z, x2, S); S = fmaf(s4.w, x3, S);
            }
            acc = fmaf(wnf[w], fmaf(C, C, S * S), acc);
        }
    }

    // Deterministic warp reduction
    #pragma unroll
    for (int o = 16; o > 0; o >>= 1)
        acc += __shfl_down_sync(0xffffffffu, acc, o);

    if (lane == 0)
        out[(b * NP + p) * NF + g * GF + f] = acc;
}

// ============================================================================
extern "C" void kernel_launch(void* const* d_in, const int* in_sizes, int n_in,
                              void* d_out, int out_size) {
    const float* x  = (const float*)d_in[0];  // (32, 64000, 1) f32
    const float* cf = (const float*)d_in[1];  // (40,) f32
    const float* bw = (const float*)d_in[2];  // (40,) f32
    const float* pw = (const float*)d_in[3];  // (40,) f32
    float* out = (float*)d_out;               // (32, 400, 40) f32

    setup_kernel<<<1, 256>>>(cf, bw, pw);

    dim3 grid(NP, NBATCH, NG);
    const size_t smem = (size_t)(XSLEN + 2 * GF * KRMAX) * sizeof(float); // ~39.6 KB
    leaf_kernel<<<grid, 320, smem>>>(x, out);
}

// round 4
// speedup vs baseline: 5.5999x; 5.5999x over previous
#include <cuda_runtime.h>
#include <math.h>

#define NF     40
#define NG     4
#define GF     10
#define TT     64000
#define NBATCH 32
#define NP     400
#define WSMAX  404
#define POSB   512          // positions per pass-1 block (256 threads x 2)
#define WGTCAP 12288        // per-group reorganized weight floats (>= cs*qn*20)

// ---- per-launch-computed meta + tables + scratch (zero-init .bss) ----
__device__ int   d_cs[NG], d_ps[NG], d_k[NG], d_qn[NG], d_ws[NG], d_L[NG];
__device__ int   d_ebase[NG];                 // energy base offset (elements) per group
__device__ float d_wgt[NG][WGTCAP];           // [r*qn + q][f*2 + {cos,sin}]
__device__ float d_win[NG][GF][WSMAX];        // pooling windows
__device__ float d_energy[81920000];          // worst case 320 * 256000 floats (328 MB)

// ============================================================================
// Setup 1: meta (cs, ps, k, qn, ws, L, energy base offsets). One tiny block.
// ============================================================================
__global__ void setup_meta(const float* __restrict__ cf,
                           const float* __restrict__ bw) {
    const int tid = threadIdx.x;
    const double Zd  = sqrt(2.0 * log(2.0)) / M_PI;
    const float bwlo = (float)(2.0   * Zd);
    const float bwhi = (float)(401.0 * Zd);
    const float pi_f = (float)M_PI;

    if (tid < NG) {
        const int g = tid;
        float cfm = 0.f, bwm = 0.f;
        for (int f = 0; f < GF; f++) {
            float c = fminf(fmaxf(cf[g * GF + f], 0.f), pi_f);
            float b = fminf(fmaxf(bw[g * GF + f], bwlo), bwhi);
            cfm = fmaxf(cfm, c);
            bwm = fmaxf(bwm, b);
        }
        double s = M_PI / (double)cfm;
        if (s < 1.0) s = 1.0;
        const int divs[12] = {160, 80, 40, 32, 20, 16, 10, 8, 5, 4, 2, 1};
        int cs = 1;
        for (int i = 0; i < 12; i++)
            if ((double)divs[i] <= s) { cs = divs[i]; break; }
        int k = (int)((double)bwm * 3.0);
        if ((k & 1) == 0) k += 1;
        int ws = (int)(401.0 / (double)cs + 0.5);
        if ((ws & 1) == 0) ws += 1;

        d_cs[g] = cs;
        d_ps[g] = 160 / cs;
        d_k[g]  = k;
        d_qn[g] = (k + cs - 1) / cs;
        d_ws[g] = ws;
        d_L[g]  = (TT - 1) / cs + 1;
    }
    __syncthreads();
    if (tid == 0) {
        int acc = 0;
        for (int g = 0; g < NG; g++) {
            d_ebase[g] = acc;
            acc += NBATCH * d_L[g] * GF;
        }
    }
}

// ============================================================================
// Setup 2: reorganized Gabor weights + pooling windows. grid (8, NG) x 256.
// ============================================================================
__global__ void setup_weights(const float* __restrict__ cf,
                              const float* __restrict__ bw,
                              const float* __restrict__ pw) {
    const int g   = blockIdx.y;
    const int cs  = d_cs[g];
    const int qn  = d_qn[g];
    const int k   = d_k[g];
    const int ws  = d_ws[g];
    const int kh  = k >> 1;

    const double Zd  = sqrt(2.0 * log(2.0)) / M_PI;
    const float bwlo = (float)(2.0   * Zd);
    const float bwhi = (float)(401.0 * Zd);
    const float pi_f = (float)M_PI;

    const int stride = gridDim.x * blockDim.x;
    const int t0 = blockIdx.x * blockDim.x + threadIdx.x;

    // weights: layout [(r*qn + q)*20 + f*2 + sel]
    const int wtot = cs * qn * 20;
    for (int i = t0; i < wtot; i += stride) {
        const int qr  = i / 20;
        const int f2  = i - qr * 20;
        const int f   = f2 >> 1;
        const int sel = f2 & 1;
        const int r   = qr / qn;
        const int q   = qr - r * qn;
        const int dw  = q * cs + r;
        float v = 0.f;
        if (dw < k) {
            const int gi = g * GF + f;
            const float cfc = fminf(fmaxf(cf[gi], 0.f), pi_f);
            const float bwc = fminf(fmaxf(bw[gi], bwlo), bwhi);
            const double t  = (double)(dw - kh);
            const double bd = (double)bwc;
            const double gauss = exp(-(t * t) / (2.0 * bd * bd));
            const double norm  = 1.0 / (sqrt(2.0 * M_PI) * bd);
            double sn, csn;
            sincos(t * (double)cfc, &sn, &csn);
            v = (float)(norm * (sel ? sn : csn) * gauss);
        }
        d_wgt[g][i] = v;
    }

    // pooling windows
    for (int i = t0; i < GF * ws; i += stride) {
        const int f = i / ws;
        const int w = i - f * ws;
        const int gi = g * GF + f;
        const float pwc = fminf(fmaxf(pw[gi], (float)(2.0 / 401.0)), 0.5f);
        const double sigma = (double)pwc / (double)cs * 401.0 / (double)ws;
        const double c = 0.5 * (double)(ws - 1);
        const double u = ((double)w - c) / (sigma * c);
        d_win[g][f][w] = (float)exp(-0.5 * u * u);
    }
}

// ============================================================================
// Pass 1: Gabor conv energy. Block = 256 threads = 512 positions, all 10
// filters per thread. x de-interleaved by residue mod cs in shared so the
// tap loads are bank-conflict-free. Weights via broadcast LDS.128.
// ============================================================================
__global__ __launch_bounds__(256) void conv_kernel(const float* __restrict__ x) {
    const int g = blockIdx.z;
    const int b = blockIdx.y;

    const int cs = d_cs[g];
    const int qn = d_qn[g];
    const int L  = d_L[g];
    const int kh = d_k[g] >> 1;

    const int j0 = blockIdx.x * POSB;
    if (j0 >= L) return;

    const int mlen  = POSB / 2 + 256 + qn;   // = 512 + qn (max m index used = 511+qn-1)
    const int mlenP = mlen | 1;              // odd row pitch -> conflict-free staging

    extern __shared__ float sm[];
    float* xr = sm;                                     // [cs][mlenP]
    const int wofs = ((cs * mlenP) + 3) & ~3;           // 16B-align weights
    float* wsm = sm + wofs;                             // [cs*qn*20]

    const int tid  = threadIdx.x;
    const int gofs = j0 * cs - kh;
    const float* xb = x + b * TT;

    // Stage x de-interleaved: xr[r][m] = x[gofs + m*cs + r], zero-padded.
    const int xtot = cs * mlen;
    for (int i = tid; i < xtot; i += 256) {
        const int gi = gofs + i;
        const float v = ((unsigned)gi < (unsigned)TT) ? xb[gi] : 0.f;
        const int r = i % cs;
        const int m = i / cs;
        xr[r * mlenP + m] = v;
    }
    // Stage reorganized weights.
    const int wtot = cs * qn * 20;
    for (int i = tid; i < wtot; i += 256)
        wsm[i] = d_wgt[g][i];
    __syncthreads();

    float C0[GF], S0[GF], C1[GF], S1[GF];
    #pragma unroll
    for (int f = 0; f < GF; f++) { C0[f] = S0[f] = C1[f] = S1[f] = 0.f; }

    #pragma unroll 1
    for (int r = 0; r < cs; r++) {
        const float* xrow = xr + r * mlenP + tid;
        const float* wrow = wsm + r * qn * 20;
        #pragma unroll 1
        for (int q = 0; q < qn; q++) {
            const float x0 = xrow[q];
            const float x1 = xrow[256 + q];
            const float4* w4 = reinterpret_cast<const float4*>(wrow + q * 20);
            #pragma unroll
            for (int c = 0; c < 5; c++) {
                const float4 w = w4[c];
                const int f0 = 2 * c, f1 = 2 * c + 1;
                C0[f0] = fmaf(w.x, x0, C0[f0]);
                S0[f0] = fmaf(w.y, x0, S0[f0]);
                C0[f1] = fmaf(w.z, x0, C0[f1]);
                S0[f1] = fmaf(w.w, x0, S0[f1]);
                C1[f0] = fmaf(w.x, x1, C1[f0]);
                S1[f0] = fmaf(w.y, x1, S1[f0]);
                C1[f1] = fmaf(w.z, x1, C1[f1]);
                S1[f1] = fmaf(w.w, x1, S1[f1]);
            }
        }
    }

    float* eb = d_energy + d_ebase[g] + b * L * GF;
    const int ja = j0 + tid;
    if (ja < L) {
        float* p = eb + ja * GF;
        #pragma unroll
        for (int h = 0; h < 5; h++) {
            float2 v;
            v.x = fmaf(C0[2*h],   C0[2*h],   S0[2*h]   * S0[2*h]);
            v.y = fmaf(C0[2*h+1], C0[2*h+1], S0[2*h+1] * S0[2*h+1]);
            reinterpret_cast<float2*>(p)[h] = v;
        }
    }
    const int jb = j0 + 256 + tid;
    if (jb < L) {
        float* p = eb + jb * GF;
        #pragma unroll
        for (int h = 0; h < 5; h++) {
            float2 v;
            v.x = fmaf(C1[2*h],   C1[2*h],   S1[2*h]   * S1[2*h]);
            v.y = fmaf(C1[2*h+1], C1[2*h+1], S1[2*h+1] * S1[2*h+1]);
            reinterpret_cast<float2*>(p)[h] = v;
        }
    }
}

// ============================================================================
// Pass 2: Gaussian pooling. Block = (8 pool positions, batch, group),
// 10 warps = 10 filters. Energy tile staged transposed (conflict-free reads).
// ============================================================================
#define PTILE 8
__global__ __launch_bounds__(320) void pool_kernel(float* __restrict__ out) {
    const int g = blockIdx.z;
    const int b = blockIdx.y;
    const int p0 = blockIdx.x * PTILE;

    const int ps  = d_ps[g];
    const int ws  = d_ws[g];
    const int L   = d_L[g];
    const int wsh = ws >> 1;

    const int jstart = p0 * ps - wsh;
    const int span   = (PTILE - 1) * ps + ws;
    const int spanP  = span | 1;

    extern __shared__ float sm[];
    float* es   = sm;                     // [GF][spanP]
    float* wins = sm + GF * spanP;        // [GF][ws]

    const int tid = threadIdx.x;
    const float* eb = d_energy + d_ebase[g] + b * L * GF;

    // Stage energy transposed: es[f][jl] = e[jstart + jl][f] (zero outside).
    for (int i = tid; i < span * GF; i += 320) {
        const int jl = i / GF;
        const int f  = i - jl * GF;
        const int gj = jstart + jl;
        const float v = ((unsigned)gj < (unsigned)L) ? eb[gj * GF + f] : 0.f;
        es[f * spanP + jl] = v;
    }
    for (int i = tid; i < GF * ws; i += 320) {
        const int f = i / ws;
        const int w = i - f * ws;
        wins[f * ws + w] = d_win[g][f][w];
    }
    __syncthreads();

    const int warp = tid >> 5;
    const int lane = tid & 31;
    const int f = warp;
    const float* wr = wins + f * ws;

    #pragma unroll 1
    for (int pl = 0; pl < PTILE; pl++) {
        const float* er = es + f * spanP + pl * ps;
        float a = 0.f;
        for (int w = lane; w < ws; w += 32)
            a = fmaf(er[w], wr[w], a);
        #pragma unroll
        for (int o = 16; o > 0; o >>= 1)
            a += __shfl_down_sync(0xffffffffu, a, o);
        if (lane == 0) {
            const int p = p0 + pl;
            out[(b * NP + p) * NF + g * GF + f] = a;
        }
    }
}

// ============================================================================
extern "C" void kernel_launch(void* const* d_in, const int* in_sizes, int n_in,
                              void* d_out, int out_size) {
    const float* x  = (const float*)d_in[0];  // (32, 64000, 1) f32
    const float* cf = (const float*)d_in[1];  // (40,) f32
    const float* bw = (const float*)d_in[2];  // (40,) f32
    const float* pw = (const float*)d_in[3];  // (40,) f32
    float* out = (float*)d_out;               // (32, 400, 40) f32

    // Opt into >48KB dynamic smem (host-side attribute; cheap and idempotent).
    cudaFuncSetAttribute(conv_kernel, cudaFuncAttributeMaxDynamicSharedMemorySize, 98304);
    cudaFuncSetAttribute(pool_kernel, cudaFuncAttributeMaxDynamicSharedMemorySize, 98304);

    setup_meta<<<1, 32>>>(cf, bw);
    setup_weights<<<dim3(8, NG), 256>>>(cf, bw, pw);

    // Pass 1: worst case L = 64000 (cs=1) -> 125 blocks of 512 positions.
    conv_kernel<<<dim3(125, NBATCH, NG), 256, 81920>>>(x);

    // Pass 2: 400 / 8 = 50 tiles.
    pool_kernel<<<dim3(NP / PTILE, NBATCH, NG), 320, 79872>>>(out);
}

// round 5
// speedup vs baseline: 6.2832x; 1.1220x over previous
#include <cuda_runtime.h>
#include <math.h>

#define NF     40
#define NG     4
#define GF     10
#define TT     64000
#define NBATCH 32
#define NP     400
#define WSMAX  404
#define POSB   512          // positions per pass-1 block (256 threads x 2)
#define WGTCAP 12288        // per-group reorganized weight floats (>= cs*qn*20)
#define CONV_SMEM 45056     // bytes: max over groups of (cs*mlenP + pad + cs*qn*20)*4
#define POOL_SMEM 16640     // bytes: GF*ws <= 4010 floats

// ---- per-launch-computed meta + tables + scratch (zero-init .bss) ----
__device__ int   d_cs[NG], d_ps[NG], d_k[NG], d_qn[NG], d_ws[NG], d_L[NG];
__device__ int   d_ebase[NG];                 // energy base offset (elements) per group
__device__ float d_wgt[NG][WGTCAP];           // [r*qn + q][f*2 + {cos,sin}]
__device__ float d_win[NG][GF][WSMAX];        // pooling windows
__device__ float d_energy[81920000];          // [g]{[f][b][j]} planes (328 MB worst case)

// ============================================================================
// Setup 1: meta (cs, ps, k, qn, ws, L, energy base offsets). One tiny block.
// ============================================================================
__global__ void setup_meta(const float* __restrict__ cf,
                           const float* __restrict__ bw) {
    const int tid = threadIdx.x;
    const double Zd  = sqrt(2.0 * log(2.0)) / M_PI;
    const float bwlo = (float)(2.0   * Zd);
    const float bwhi = (float)(401.0 * Zd);
    const float pi_f = (float)M_PI;

    if (tid < NG) {
        const int g = tid;
        float cfm = 0.f, bwm = 0.f;
        for (int f = 0; f < GF; f++) {
            float c = fminf(fmaxf(cf[g * GF + f], 0.f), pi_f);
            float b = fminf(fmaxf(bw[g * GF + f], bwlo), bwhi);
            cfm = fmaxf(cfm, c);
            bwm = fmaxf(bwm, b);
        }
        double s = M_PI / (double)cfm;
        if (s < 1.0) s = 1.0;
        const int divs[12] = {160, 80, 40, 32, 20, 16, 10, 8, 5, 4, 2, 1};
        int cs = 1;
        for (int i = 0; i < 12; i++)
            if ((double)divs[i] <= s) { cs = divs[i]; break; }
        int k = (int)((double)bwm * 3.0);
        if ((k & 1) == 0) k += 1;
        int ws = (int)(401.0 / (double)cs + 0.5);
        if ((ws & 1) == 0) ws += 1;

        d_cs[g] = cs;
        d_ps[g] = 160 / cs;
        d_k[g]  = k;
        d_qn[g] = (k + cs - 1) / cs;
        d_ws[g] = ws;
        d_L[g]  = (TT - 1) / cs + 1;
    }
    __syncthreads();
    if (tid == 0) {
        int acc = 0;
        for (int g = 0; g < NG; g++) {
            d_ebase[g] = acc;
            acc += NBATCH * d_L[g] * GF;
        }
    }
}

// ============================================================================
// Setup 2: reorganized Gabor weights + pooling windows. grid (8, NG) x 256.
// ============================================================================
__global__ void setup_weights(const float* __restrict__ cf,
                              const float* __restrict__ bw,
                              const float* __restrict__ pw) {
    const int g   = blockIdx.y;
    const int cs  = d_cs[g];
    const int qn  = d_qn[g];
    const int k   = d_k[g];
    const int ws  = d_ws[g];
    const int kh  = k >> 1;

    const double Zd  = sqrt(2.0 * log(2.0)) / M_PI;
    const float bwlo = (float)(2.0   * Zd);
    const float bwhi = (float)(401.0 * Zd);
    const float pi_f = (float)M_PI;

    const int stride = gridDim.x * blockDim.x;
    const int t0 = blockIdx.x * blockDim.x + threadIdx.x;

    // weights: layout [(r*qn + q)*20 + f*2 + sel]
    const int wtot = cs * qn * 20;
    for (int i = t0; i < wtot; i += stride) {
        const int qr  = i / 20;
        const int f2  = i - qr * 20;
        const int f   = f2 >> 1;
        const int sel = f2 & 1;
        const int r   = qr / qn;
        const int q   = qr - r * qn;
        const int dw  = q * cs + r;
        float v = 0.f;
        if (dw < k) {
            const int gi = g * GF + f;
            const float cfc = fminf(fmaxf(cf[gi], 0.f), pi_f);
            const float bwc = fminf(fmaxf(bw[gi], bwlo), bwhi);
            const double t  = (double)(dw - kh);
            const double bd = (double)bwc;
            const double gauss = exp(-(t * t) / (2.0 * bd * bd));
            const double norm  = 1.0 / (sqrt(2.0 * M_PI) * bd);
            double sn, csn;
            sincos(t * (double)cfc, &sn, &csn);
            v = (float)(norm * (sel ? sn : csn) * gauss);
        }
        d_wgt[g][i] = v;
    }

    // pooling windows
    for (int i = t0; i < GF * ws; i += stride) {
        const int f = i / ws;
        const int w = i - f * ws;
        const int gi = g * GF + f;
        const float pwc = fminf(fmaxf(pw[gi], (float)(2.0 / 401.0)), 0.5f);
        const double sigma = (double)pwc / (double)cs * 401.0 / (double)ws;
        const double c = 0.5 * (double)(ws - 1);
        const double u = ((double)w - c) / (sigma * c);
        d_win[g][f][w] = (float)exp(-0.5 * u * u);
    }
}

// ============================================================================
// Pass 1: Gabor conv energy. Block = 256 threads = 512 positions, all 10
// filters per thread. x de-interleaved by residue mod cs in shared so the
// tap loads are bank-conflict-free. Weights via broadcast LDS.128.
// Energy written as [f][b][j] planes -> coalesced 128B stores per filter.
// ============================================================================
__global__ __launch_bounds__(256) void conv_kernel(const float* __restrict__ x) {
    const int g = blockIdx.z;
    const int b = blockIdx.y;

    const int cs = d_cs[g];
    const int qn = d_qn[g];
    const int L  = d_L[g];
    const int kh = d_k[g] >> 1;

    const int j0 = blockIdx.x * POSB;
    if (j0 >= L) return;

    const int mlen  = POSB / 2 + 256 + qn;   // = 512 + qn
    const int mlenP = mlen | 1;              // odd row pitch -> conflict-free staging

    extern __shared__ float sm[];
    float* xr = sm;                                     // [cs][mlenP]
    const int wofs = ((cs * mlenP) + 3) & ~3;           // 16B-align weights
    float* wsm = sm + wofs;                             // [cs*qn*20]

    const int tid  = threadIdx.x;
    const int gofs = j0 * cs - kh;
    const float* xb = x + b * TT;

    // Stage x de-interleaved: xr[r][m] = x[gofs + m*cs + r], zero-padded.
    const int xtot = cs * mlen;
    for (int i = tid; i < xtot; i += 256) {
        const int gi = gofs + i;
        const float v = ((unsigned)gi < (unsigned)TT) ? xb[gi] : 0.f;
        const int r = i % cs;
        const int m = i / cs;
        xr[r * mlenP + m] = v;
    }
    // Stage reorganized weights.
    const int wtot = cs * qn * 20;
    for (int i = tid; i < wtot; i += 256)
        wsm[i] = d_wgt[g][i];
    __syncthreads();

    float C0[GF], S0[GF], C1[GF], S1[GF];
    #pragma unroll
    for (int f = 0; f < GF; f++) { C0[f] = S0[f] = C1[f] = S1[f] = 0.f; }

    #pragma unroll 1
    for (int r = 0; r < cs; r++) {
        const float* xrow = xr + r * mlenP + tid;
        const float* wrow = wsm + r * qn * 20;
        #pragma unroll 1
        for (int q = 0; q < qn; q++) {
            const float x0 = xrow[q];
            const float x1 = xrow[256 + q];
            const float4* w4 = reinterpret_cast<const float4*>(wrow + q * 20);
            #pragma unroll
            for (int c = 0; c < 5; c++) {
                const float4 w = w4[c];
                const int f0 = 2 * c, f1 = 2 * c + 1;
                C0[f0] = fmaf(w.x, x0, C0[f0]);
                S0[f0] = fmaf(w.y, x0, S0[f0]);
                C0[f1] = fmaf(w.z, x0, C0[f1]);
                S0[f1] = fmaf(w.w, x0, S0[f1]);
                C1[f0] = fmaf(w.x, x1, C1[f0]);
                S1[f0] = fmaf(w.y, x1, S1[f0]);
                C1[f1] = fmaf(w.z, x1, C1[f1]);
                S1[f1] = fmaf(w.w, x1, S1[f1]);
            }
        }
    }

    // Transposed (plane) stores: e[f][b][j]. Warp writes 32 consecutive j.
    float* eg = d_energy + d_ebase[g];
    const int ja = j0 + tid;
    const int jb = j0 + 256 + tid;
    #pragma unroll
    for (int f = 0; f < GF; f++) {
        float* pf = eg + (f * NBATCH + b) * L;
        if (ja < L) pf[ja] = fmaf(C0[f], C0[f], S0[f] * S0[f]);
        if (jb < L) pf[jb] = fmaf(C1[f], C1[f], S1[f] * S1[f]);
    }
}

// ============================================================================
// Pass 2: Gaussian pooling from [f][b][j] planes. Grid (4 p-tiles, b, g),
// block 512 threads = 16 warps. Warp handles one (f, p) output at a time:
// lanes stride the window with coalesced global reads; win staged in smem.
// ============================================================================
#define PTW 100   // pool positions per tile (NP / 4)
__global__ __launch_bounds__(512) void pool_kernel(float* __restrict__ out) {
    const int g  = blockIdx.z;
    const int b  = blockIdx.y;
    const int p0 = blockIdx.x * PTW;

    const int ps  = d_ps[g];
    const int ws  = d_ws[g];
    const int L   = d_L[g];
    const int wsh = ws >> 1;

    extern __shared__ float wins[];   // [GF][ws]
    const int tid = threadIdx.x;
    for (int i = tid; i < GF * ws; i += 512)
        wins[i] = (&d_win[g][0][0])[(i / ws) * WSMAX + (i % ws)];
    __syncthreads();

    const int warp = tid >> 5;
    const int lane = tid & 31;
    const float* eg = d_energy + d_ebase[g];

    // tasks: idx = f * PTW + pl  (f-major so adjacent warps share windows/planes)
    for (int idx = warp; idx < GF * PTW; idx += 16) {
        const int f  = idx / PTW;
        const int pl = idx - f * PTW;
        const int p  = p0 + pl;
        const int jstart = p * ps - wsh;

        const float* ef = eg + (f * NBATCH + b) * L;
        const float* wr = wins + f * ws;

        float a = 0.f;
        for (int w = lane; w < ws; w += 32) {
            const int j = jstart + w;
            if ((unsigned)j < (unsigned)L)
                a = fmaf(wr[w], __ldg(ef + j), a);
        }
        #pragma unroll
        for (int o = 16; o > 0; o >>= 1)
            a += __shfl_down_sync(0xffffffffu, a, o);
        if (lane == 0)
            out[(b * NP + p) * NF + g * GF + f] = a;
    }
}

// ============================================================================
extern "C" void kernel_launch(void* const* d_in, const int* in_sizes, int n_in,
                              void* d_out, int out_size) {
    const float* x  = (const float*)d_in[0];  // (32, 64000, 1) f32
    const float* cf = (const float*)d_in[1];  // (40,) f32
    const float* bw = (const float*)d_in[2];  // (40,) f32
    const float* pw = (const float*)d_in[3];  // (40,) f32
    float* out = (float*)d_out;               // (32, 400, 40) f32

    cudaFuncSetAttribute(conv_kernel, cudaFuncAttributeMaxDynamicSharedMemorySize, CONV_SMEM);
    cudaFuncSetAttribute(pool_kernel, cudaFuncAttributeMaxDynamicSharedMemorySize, POOL_SMEM);

    setup_meta<<<1, 32>>>(cf, bw);
    setup_weights<<<dim3(8, NG), 256>>>(cf, bw, pw);

    // Pass 1: worst case L = 64000 (cs=1) -> 125 blocks of 512 positions.
    conv_kernel<<<dim3(125, NBATCH, NG), 256, CONV_SMEM>>>(x);

    // Pass 2: 4 tiles of 100 pool positions.
    pool_kernel<<<dim3(NP / PTW, NBATCH, NG), 512, POOL_SMEM>>>(out);
}

// round 6
// speedup vs baseline: 8.7181x; 1.3875x over previous
#include <cuda_runtime.h>
#include <math.h>

#define NF     40
#define NG     4
#define GF     10
#define TT     64000
#define NBATCH 32
#define NP     400
#define WSMAX  404
#define POSB   512          // positions per pass-1 block (256 threads x 2)
#define WGTCAP 8192         // per-group reorganized weight floats (cs*qmA*20 + 12)
#define CONV_SMEM 43008
#define POOL_SMEM 16640     // GF*ws <= 4010 floats

// ---- per-launch-computed meta + tables + scratch (zero-init .bss) ----
__device__ int   d_cs[NG], d_ps[NG], d_k[NG], d_qn[NG], d_qm[NG], d_ws[NG], d_L[NG];
__device__ int   d_ebase[NG];                 // energy base offset (elements) per group
__device__ float d_wgt[NG][WGTCAP];           // [r][q][f*2+{cos,sin}] pairs + center norms
__device__ float d_win[NG][GF][WSMAX];        // pooling windows
__device__ float d_energy[81920000];          // [g]{[f][b][j]} planes

// ============================================================================
// Setup 1: meta. One tiny block.
// ============================================================================
__global__ void setup_meta(const float* __restrict__ cf,
                           const float* __restrict__ bw) {
    const int tid = threadIdx.x;
    const double Zd  = sqrt(2.0 * log(2.0)) / M_PI;
    const float bwlo = (float)(2.0   * Zd);
    const float bwhi = (float)(401.0 * Zd);
    const float pi_f = (float)M_PI;

    if (tid < NG) {
        const int g = tid;
        float cfm = 0.f, bwm = 0.f;
        for (int f = 0; f < GF; f++) {
            float c = fminf(fmaxf(cf[g * GF + f], 0.f), pi_f);
            float b = fminf(fmaxf(bw[g * GF + f], bwlo), bwhi);
            cfm = fmaxf(cfm, c);
            bwm = fmaxf(bwm, b);
        }
        double s = M_PI / (double)cfm;
        if (s < 1.0) s = 1.0;
        const int divs[12] = {160, 80, 40, 32, 20, 16, 10, 8, 5, 4, 2, 1};
        int cs = 1;
        for (int i = 0; i < 12; i++)
            if ((double)divs[i] <= s) { cs = divs[i]; break; }
        int k = (int)((double)bwm * 3.0);
        if ((k & 1) == 0) k += 1;
        int ws = (int)(401.0 / (double)cs + 0.5);
        if ((ws & 1) == 0) ws += 1;

        const int kh = k >> 1;
        d_cs[g] = cs;
        d_ps[g] = 160 / cs;
        d_k[g]  = k;
        d_qn[g] = (k + cs - 1) / cs;
        d_qm[g] = kh / cs + 1;        // pair-slot count per residue
        d_ws[g] = ws;
        d_L[g]  = (TT - 1) / cs + 1;
    }
    __syncthreads();
    if (tid == 0) {
        int acc = 0;
        for (int g = 0; g < NG; g++) {
            d_ebase[g] = acc;
            acc += NBATCH * d_L[g] * GF;
        }
    }
}

// ============================================================================
// Setup 2: symmetric-pair Gabor weights + pooling windows. grid (8, NG) x 256.
// Pair (r, q) -> tap t = q*cs + r (t in [1, kh]); slot holds
// [f*2+0] = norm*cos(t*cf)*gauss(t)  (applied to x+ + x-)
// [f*2+1] = norm*sin(t*cf)*gauss(t)  (applied to x+ - x-)
// Center norms (t=0) appended at offset cs*qmA*20 (10 floats, 2 pad zeros).
// ============================================================================
__global__ void setup_weights(const float* __restrict__ cf,
                              const float* __restrict__ bw,
                              const float* __restrict__ pw) {
    const int g   = blockIdx.y;
    const int cs  = d_cs[g];
    const int qmA = d_qm[g];
    const int k   = d_k[g];
    const int ws  = d_ws[g];
    const int kh  = k >> 1;

    const double Zd  = sqrt(2.0 * log(2.0)) / M_PI;
    const float bwlo = (float)(2.0   * Zd);
    const float bwhi = (float)(401.0 * Zd);
    const float pi_f = (float)M_PI;

    const int stride = gridDim.x * blockDim.x;
    const int t0 = blockIdx.x * blockDim.x + threadIdx.x;

    const int wtot = cs * qmA * 20;
    for (int i = t0; i < wtot; i += stride) {
        const int qr  = i / 20;
        const int f2  = i - qr * 20;
        const int f   = f2 >> 1;
        const int sel = f2 & 1;
        const int r   = qr / qmA;
        const int q   = qr - r * qmA;
        const int t   = q * cs + r;
        float v = 0.f;
        if (t >= 1 && t <= kh) {
            const int gi = g * GF + f;
            const float cfc = fminf(fmaxf(cf[gi], 0.f), pi_f);
            const float bwc = fminf(fmaxf(bw[gi], bwlo), bwhi);
            const double td = (double)t;
            const double bd = (double)bwc;
            const double gauss = exp(-(td * td) / (2.0 * bd * bd));
            const double norm  = 1.0 / (sqrt(2.0 * M_PI) * bd);
            double sn, csn;
            sincos(td * (double)cfc, &sn, &csn);
            v = (float)(norm * (sel ? sn : csn) * gauss);
        }
        d_wgt[g][i] = v;
    }
    // center norms
    for (int i = t0; i < GF; i += stride) {
        const int gi = g * GF + i;
        const float bwc = fminf(fmaxf(bw[gi], bwlo), bwhi);
        d_wgt[g][wtot + i] = (float)(1.0 / (sqrt(2.0 * M_PI) * (double)bwc));
    }
    if (t0 < 2) d_wgt[g][wtot + GF + t0] = 0.f;   // pad for float4 reads

    // pooling windows
    for (int i = t0; i < GF * ws; i += stride) {
        const int f = i / ws;
        const int w = i - f * ws;
        const int gi = g * GF + f;
        const float pwc = fminf(fmaxf(pw[gi], (float)(2.0 / 401.0)), 0.5f);
        const double sigma = (double)pwc / (double)cs * 401.0 / (double)ws;
        const double c = 0.5 * (double)(ws - 1);
        const double u = ((double)w - c) / (sigma * c);
        d_win[g][f][w] = (float)exp(-0.5 * u * u);
    }
}

// ============================================================================
// Pass 1: symmetric Gabor conv energy. 256 threads = 512 positions, all 10
// filters per thread. Even/odd symmetry: per tap-pair shared u = x+ + x-,
// d = x+ - x- feed 20 FMAs (vs 40 for two raw taps).
// ============================================================================
__global__ __launch_bounds__(256) void conv_kernel(const float* __restrict__ x) {
    const int g = blockIdx.z;
    const int b = blockIdx.y;

    const int cs  = d_cs[g];
    const int qn  = d_qn[g];
    const int qmA = d_qm[g];
    const int L   = d_L[g];
    const int kh  = d_k[g] >> 1;

    const int j0 = blockIdx.x * POSB;
    if (j0 >= L) return;

    const int mlen  = POSB / 2 + 256 + qn;
    const int mlenP = mlen | 1;

    extern __shared__ float sm[];
    float* xr = sm;                                     // [cs][mlenP]
    const int wofs = ((cs * mlenP) + 3) & ~3;
    float* wsm = sm + wofs;                             // pairs + center

    const int tid  = threadIdx.x;
    const int gofs = j0 * cs - kh;
    const float* xb = x + b * TT;

    // Stage x de-interleaved: xr[r][m] = x[gofs + m*cs + r], zero-padded.
    const int xtot = cs * mlen;
    for (int i = tid; i < xtot; i += 256) {
        const int gi = gofs + i;
        const float v = ((unsigned)gi < (unsigned)TT) ? xb[gi] : 0.f;
        const int r = i % cs;
        const int m = i / cs;
        xr[r * mlenP + m] = v;
    }
    const int wtot = cs * qmA * 20 + 12;
    for (int i = tid; i < wtot; i += 256)
        wsm[i] = d_wgt[g][i];
    __syncthreads();

    float C0[GF], S0[GF], C1[GF], S1[GF];
    #pragma unroll
    for (int f = 0; f < GF; f++) { C0[f] = S0[f] = C1[f] = S1[f] = 0.f; }

    // Center tap (t = 0): contributes only to C (sin(0)=0).
    {
        const float* rowC = xr + (kh % cs) * mlenP + (kh / cs) + tid;
        const float xc0 = rowC[0];
        const float xc1 = rowC[256];
        const float4* c4 = reinterpret_cast<const float4*>(wsm + cs * qmA * 20);
        const float4 n0 = c4[0], n1 = c4[1], n2 = c4[2];
        C0[0] = fmaf(n0.x, xc0, C0[0]); C1[0] = fmaf(n0.x, xc1, C1[0]);
        C0[1] = fmaf(n0.y, xc0, C0[1]); C1[1] = fmaf(n0.y, xc1, C1[1]);
        C0[2] = fmaf(n0.z, xc0, C0[2]); C1[2] = fmaf(n0.z, xc1, C1[2]);
        C0[3] = fmaf(n0.w, xc0, C0[3]); C1[3] = fmaf(n0.w, xc1, C1[3]);
        C0[4] = fmaf(n1.x, xc0, C0[4]); C1[4] = fmaf(n1.x, xc1, C1[4]);
        C0[5] = fmaf(n1.y, xc0, C0[5]); C1[5] = fmaf(n1.y, xc1, C1[5]);
        C0[6] = fmaf(n1.z, xc0, C0[6]); C1[6] = fmaf(n1.z, xc1, C1[6]);
        C0[7] = fmaf(n1.w, xc0, C0[7]); C1[7] = fmaf(n1.w, xc1, C1[7]);
        C0[8] = fmaf(n2.x, xc0, C0[8]); C1[8] = fmaf(n2.x, xc1, C1[8]);
        C0[9] = fmaf(n2.y, xc0, C0[9]); C1[9] = fmaf(n2.y, xc1, C1[9]);
    }

    // Tap pairs t = q*cs + r, t in [1, kh].
    #pragma unroll 1
    for (int r = 0; r < cs; r++) {
        const int qlo = (r == 0) ? 1 : 0;
        const int aM  = (kh - r) / cs;        // == qhi (inclusive)
        const int sM  = (kh - r) % cs;
        const int bP  = (kh + r) / cs;
        const int sP  = (kh + r) % cs;
        const float* rowP = xr + sP * mlenP + tid + bP;
        const float* rowM = xr + sM * mlenP + tid + aM;
        const float* wr = wsm + r * qmA * 20;
        #pragma unroll 1
        for (int q = qlo; q <= aM; q++) {
            const float xp0 = rowP[q];
            const float xm0 = rowM[-q];
            const float xp1 = rowP[256 + q];
            const float xm1 = rowM[256 - q];
            const float u0 = xp0 + xm0, dd0 = xp0 - xm0;
            const float u1 = xp1 + xm1, dd1 = xp1 - xm1;
            const float4* w4 = reinterpret_cast<const float4*>(wr + q * 20);
            #pragma unroll
            for (int c = 0; c < 5; c++) {
                const float4 w = w4[c];
                const int f0 = 2 * c, f1 = 2 * c + 1;
                C0[f0] = fmaf(w.x, u0,  C0[f0]);
                S0[f0] = fmaf(w.y, dd0, S0[f0]);
                C0[f1] = fmaf(w.z, u0,  C0[f1]);
                S0[f1] = fmaf(w.w, dd0, S0[f1]);
                C1[f0] = fmaf(w.x, u1,  C1[f0]);
                S1[f0] = fmaf(w.y, dd1, S1[f0]);
                C1[f1] = fmaf(w.z, u1,  C1[f1]);
                S1[f1] = fmaf(w.w, dd1, S1[f1]);
            }
        }
    }

    // Plane stores: e[f][b][j] — coalesced per filter.
    float* eg = d_energy + d_ebase[g];
    const int ja = j0 + tid;
    const int jb = j0 + 256 + tid;
    #pragma unroll
    for (int f = 0; f < GF; f++) {
        float* pf = eg + (f * NBATCH + b) * L;
        if (ja < L) pf[ja] = fmaf(C0[f], C0[f], S0[f] * S0[f]);
        if (jb < L) pf[jb] = fmaf(C1[f], C1[f], S1[f] * S1[f]);
    }
}

// ============================================================================
// Pass 2: Gaussian pooling from [f][b][j] planes. Warp per output; hoisted
// clamped window bounds (no per-iter checks), unroll x2, coalesced LDG.
// ============================================================================
#define PTW 100
__global__ __launch_bounds__(512) void pool_kernel(float* __restrict__ out) {
    const int g  = blockIdx.z;
    const int b  = blockIdx.y;
    const int p0 = blockIdx.x * PTW;

    const int ps  = d_ps[g];
    const int ws  = d_ws[g];
    const int L   = d_L[g];
    const int wsh = ws >> 1;

    extern __shared__ float wins[];   // [GF][ws]
    const int tid = threadIdx.x;
    for (int i = tid; i < GF * ws; i += 512)
        wins[i] = (&d_win[g][0][0])[(i / ws) * WSMAX + (i % ws)];
    __syncthreads();

    const int warp = tid >> 5;
    const int lane = tid & 31;
    const float* eg = d_energy + d_ebase[g];

    for (int idx = warp; idx < GF * PTW; idx += 16) {
        const int f  = idx / PTW;
        const int pl = idx - f * PTW;
        const int p  = p0 + pl;
        const int jstart = p * ps - wsh;

        int wlo = (jstart < 0) ? -jstart : 0;
        int whi = (jstart + ws > L) ? (L - jstart) : ws;

        const float* ep = eg + (f * NBATCH + b) * L + jstart;
        const float* wr = wins + f * ws;

        float a0 = 0.f, a1 = 0.f;
        int w = wlo + lane;
        #pragma unroll 1
        for (; w + 32 < whi; w += 64) {
            a0 = fmaf(wr[w],      __ldg(ep + w),      a0);
            a1 = fmaf(wr[w + 32], __ldg(ep + w + 32), a1);
        }
        if (w < whi) a0 = fmaf(wr[w], __ldg(ep + w), a0);
        a0 += a1;
        #pragma unroll
        for (int o = 16; o > 0; o >>= 1)
            a0 += __shfl_down_sync(0xffffffffu, a0, o);
        if (lane == 0)
            out[(b * NP + p) * NF + g * GF + f] = a0;
    }
}

// ============================================================================
extern "C" void kernel_launch(void* const* d_in, const int* in_sizes, int n_in,
                              void* d_out, int out_size) {
    const float* x  = (const float*)d_in[0];  // (32, 64000, 1) f32
    const float* cf = (const float*)d_in[1];  // (40,) f32
    const float* bw = (const float*)d_in[2];  // (40,) f32
    const float* pw = (const float*)d_in[3];  // (40,) f32
    float* out = (float*)d_out;               // (32, 400, 40) f32

    cudaFuncSetAttribute(conv_kernel, cudaFuncAttributeMaxDynamicSharedMemorySize, CONV_SMEM);
    cudaFuncSetAttribute(pool_kernel, cudaFuncAttributeMaxDynamicSharedMemorySize, POOL_SMEM);

    setup_meta<<<1, 32>>>(cf, bw);
    setup_weights<<<dim3(8, NG), 256>>>(cf, bw, pw);

    conv_kernel<<<dim3(125, NBATCH, NG), 256, CONV_SMEM>>>(x);
    pool_kernel<<<dim3(NP / PTW, NBATCH, NG), 512, POOL_SMEM>>>(out);
}

// round 8
// speedup vs baseline: 8.7721x; 1.0062x over previous
#include <cuda_runtime.h>
#include <math.h>

#define NF     40
#define NG     4
#define GF     10
#define TT     64000
#define NBATCH 32
#define NP     400
#define WSMAX  404
#define POSB   512          // positions per pass-1 block (256 threads x 2)
#define WGTCAP 6144         // per-group weight floats (cs*qm*40 + 12), max 6012
#define CONV_SMEM 46080
#define POOL_SMEM 46080
#define PT     64           // pool outputs per block
#define PSUB   8            // w-segments per output
// pool smem float offsets
#define ES_OFF   0
#define WIN_OFF  10496      // es span max = 63*160+401 = 10481
#define PART_OFF 10912      // wins <= 401
// total floats = 10912 + 512 = 11424 -> 45696 B

// ---- packed f32x2 helpers (sm_100+ PTX) ----
#define PACKX2(out, lo, hi) \
    asm("mov.b64 %0, {%1, %2};" : "=l"(out) : "f"(lo), "f"(hi))
#define UNPACKX2(lo, hi, in) \
    asm("mov.b64 {%0, %1}, %2;" : "=f"(lo), "=f"(hi) : "l"(in))
#define ADDX2(out, a, b) \
    asm("add.rn.f32x2 %0, %1, %2;" : "=l"(out) : "l"(a), "l"(b))
#define FMAX2(acc, a, b) \
    asm("fma.rn.f32x2 %0, %1, %2, %0;" : "+l"(acc) : "l"(a), "l"(b))

// ---- per-launch-computed meta + tables + scratch (zero-init .bss) ----
__device__ int   d_cs[NG], d_ps[NG], d_k[NG], d_qn[NG], d_qm[NG], d_ws[NG], d_L[NG];
__device__ int   d_ebase[NG];
__device__ float d_wgt[NG][WGTCAP];           // [r][q][f][wc,wc,ws,ws] + center norms
__device__ float d_win[NG][GF][WSMAX];
__device__ float d_energy[81920000];          // [g]{[f][b][j]} planes

// ============================================================================
// Setup 1: meta. One tiny block.
// ============================================================================
__global__ void setup_meta(const float* __restrict__ cf,
                           const float* __restrict__ bw) {
    const int tid = threadIdx.x;
    const double Zd  = sqrt(2.0 * log(2.0)) / M_PI;
    const float bwlo = (float)(2.0   * Zd);
    const float bwhi = (float)(401.0 * Zd);
    const float pi_f = (float)M_PI;

    if (tid < NG) {
        const int g = tid;
        float cfm = 0.f, bwm = 0.f;
        for (int f = 0; f < GF; f++) {
            float c = fminf(fmaxf(cf[g * GF + f], 0.f), pi_f);
            float b = fminf(fmaxf(bw[g * GF + f], bwlo), bwhi);
            cfm = fmaxf(cfm, c);
            bwm = fmaxf(bwm, b);
        }
        double s = M_PI / (double)cfm;
        if (s < 1.0) s = 1.0;
        const int divs[12] = {160, 80, 40, 32, 20, 16, 10, 8, 5, 4, 2, 1};
        int cs = 1;
        for (int i = 0; i < 12; i++)
            if ((double)divs[i] <= s) { cs = divs[i]; break; }
        int k = (int)((double)bwm * 3.0);
        if ((k & 1) == 0) k += 1;
        int ws = (int)(401.0 / (double)cs + 0.5);
        if ((ws & 1) == 0) ws += 1;

        const int kh = k >> 1;
        d_cs[g] = cs;
        d_ps[g] = 160 / cs;
        d_k[g]  = k;
        d_qn[g] = (k + cs - 1) / cs;
        d_qm[g] = kh / cs + 1;
        d_ws[g] = ws;
        d_L[g]  = (TT - 1) / cs + 1;
    }
    __syncthreads();
    if (tid == 0) {
        int acc = 0;
        for (int g = 0; g < NG; g++) {
            d_ebase[g] = acc;
            acc += NBATCH * d_L[g] * GF;
        }
    }
}

// ============================================================================
// Setup 2: symmetric-pair Gabor weights (duplicated for f32x2) + pool windows.
// Pair slot (r, q) -> tap t = q*cs + r (t in [1, kh]); slot = 40 floats:
// for f in 0..9: [wc_f, wc_f, ws_f, ws_f]  (16B per filter -> LDS.128)
// Center norms appended at cs*qm*40 (10 floats + 2 pad).
// ============================================================================
__global__ void setup_weights(const float* __restrict__ cf,
                              const float* __restrict__ bw,
                              const float* __restrict__ pw) {
    const int g   = blockIdx.y;
    const int cs  = d_cs[g];
    const int qmA = d_qm[g];
    const int k   = d_k[g];
    const int ws  = d_ws[g];
    const int kh  = k >> 1;

    const double Zd  = sqrt(2.0 * log(2.0)) / M_PI;
    const float bwlo = (float)(2.0   * Zd);
    const float bwhi = (float)(401.0 * Zd);
    const float pi_f = (float)M_PI;

    const int stride = gridDim.x * blockDim.x;
    const int t0 = blockIdx.x * blockDim.x + threadIdx.x;

    const int wtot = cs * qmA * 40;
    for (int i = t0; i < wtot; i += stride) {
        const int qr  = i / 40;
        const int rem = i - qr * 40;
        const int f   = rem >> 2;
        const int sel = (rem & 3) >> 1;       // 0,1 -> cos ; 2,3 -> sin
        const int r   = qr / qmA;
        const int q   = qr - r * qmA;
        const int t   = q * cs + r;
        float v = 0.f;
        if (t >= 1 && t <= kh) {
            const int gi = g * GF + f;
            const float cfc = fminf(fmaxf(cf[gi], 0.f), pi_f);
            const float bwc = fminf(fmaxf(bw[gi], bwlo), bwhi);
            const double td = (double)t;
            const double bd = (double)bwc;
            const double gauss = exp(-(td * td) / (2.0 * bd * bd));
            const double norm  = 1.0 / (sqrt(2.0 * M_PI) * bd);
            double sn, csn;
            sincos(td * (double)cfc, &sn, &csn);
            v = (float)(norm * (sel ? sn : csn) * gauss);
        }
        d_wgt[g][i] = v;
    }
    for (int i = t0; i < GF; i += stride) {
        const int gi = g * GF + i;
        const float bwc = fminf(fmaxf(bw[gi], bwlo), bwhi);
        d_wgt[g][wtot + i] = (float)(1.0 / (sqrt(2.0 * M_PI) * (double)bwc));
    }
    if (t0 < 2) d_wgt[g][wtot + GF + t0] = 0.f;

    for (int i = t0; i < GF * ws; i += stride) {
        const int f = i / ws;
        const int w = i - f * ws;
        const int gi = g * GF + f;
        const float pwc = fminf(fmaxf(pw[gi], (float)(2.0 / 401.0)), 0.5f);
        const double sigma = (double)pwc / (double)cs * 401.0 / (double)ws;
        const double c = 0.5 * (double)(ws - 1);
        const double u = ((double)w - c) / (sigma * c);
        d_win[g][f][w] = (float)exp(-0.5 * u * u);
    }
}

// ============================================================================
// Pass 1: symmetric Gabor conv energy with packed f32x2 math.
// Two positions per thread packed as the two f32 lanes of each accumulator.
// ============================================================================
__global__ __launch_bounds__(256) void conv_kernel(const float* __restrict__ x) {
    const int g = blockIdx.z;
    const int b = blockIdx.y;

    const int cs  = d_cs[g];
    const int qn  = d_qn[g];
    const int qmA = d_qm[g];
    const int L   = d_L[g];
    const int kh  = d_k[g] >> 1;

    const int j0 = blockIdx.x * POSB;
    if (j0 >= L) return;

    const int mlen  = POSB / 2 + 256 + qn;
    const int mlenP = mlen | 1;

    extern __shared__ float sm[];
    float* xr = sm;                                     // [cs][mlenP]
    const int wofs = ((cs * mlenP) + 3) & ~3;
    float* wsm = sm + wofs;

    const int tid  = threadIdx.x;
    const int gofs = j0 * cs - kh;
    const float* xb = x + b * TT;

    const int xtot = cs * mlen;
    for (int i = tid; i < xtot; i += 256) {
        const int gi = gofs + i;
        const float v = ((unsigned)gi < (unsigned)TT) ? xb[gi] : 0.f;
        const int r = i % cs;
        const int m = i / cs;
        xr[r * mlenP + m] = v;
    }
    const int wtot = cs * qmA * 40 + 12;
    for (int i = tid; i < wtot; i += 256)
        wsm[i] = d_wgt[g][i];
    __syncthreads();

    unsigned long long C01[GF], S01[GF];

    // Center tap (t=0): init C accumulators (sin(0)=0 -> S=0).
    {
        const float* rowC = xr + (kh % cs) * mlenP + (kh / cs) + tid;
        const float xc0 = rowC[0];
        const float xc1 = rowC[256];
        const float* nrm = wsm + cs * qmA * 40;
        #pragma unroll
        for (int f = 0; f < GF; f++) {
            const float n = nrm[f];
            PACKX2(C01[f], n * xc0, n * xc1);
            PACKX2(S01[f], 0.f, 0.f);
        }
    }

    // Tap pairs t = q*cs + r, t in [1, kh].
    #pragma unroll 1
    for (int r = 0; r < cs; r++) {
        const int qlo = (r == 0) ? 1 : 0;
        const int aM  = (kh - r) / cs;
        const int sM  = (kh - r) % cs;
        const int bP  = (kh + r) / cs;
        const int sP  = (kh + r) % cs;
        const float* rowP = xr + sP * mlenP + tid + bP;
        const float* rowM = xr + sM * mlenP + tid + aM;
        const float* wr = wsm + r * qmA * 40;
        #pragma unroll 1
        for (int q = qlo; q <= aM; q++) {
            const float xp0 = rowP[q];
            const float xm0 = rowM[-q];
            const float xp1 = rowP[256 + q];
            const float xm1 = rowM[256 - q];
            unsigned long long xp, xm, u, d;
            PACKX2(xp, xp0, xp1);
            PACKX2(xm, xm0, xm1);
            ADDX2(u, xp, xm);
            PACKX2(d, xp0 - xm0, xp1 - xm1);
            const ulonglong2* w2 = reinterpret_cast<const ulonglong2*>(wr + q * 40);
            #pragma unroll
            for (int f = 0; f < GF; f++) {
                const ulonglong2 wp = w2[f];   // .x = (wc,wc), .y = (ws,ws)
                FMAX2(C01[f], wp.x, u);
                FMAX2(S01[f], wp.y, d);
            }
        }
    }

    // Plane stores: e[f][b][j] — coalesced per filter.
    float* eg = d_energy + d_ebase[g];
    const int ja = j0 + tid;
    const int jb = j0 + 256 + tid;
    #pragma unroll
    for (int f = 0; f < GF; f++) {
        float c0, c1, s0, s1;
        UNPACKX2(c0, c1, C01[f]);
        UNPACKX2(s0, s1, S01[f]);
        float* pf = eg + (f * NBATCH + b) * L;
        if (ja < L) pf[ja] = fmaf(c0, c0, s0 * s0);
        if (jb < L) pf[jb] = fmaf(c1, c1, s1 * s1);
    }
}

// ============================================================================
// Pass 2: pooling, thread-per-output from smem-staged energy.
// Block = (p-tile of 64, b, g*f). 512 threads = 64 outputs x 8 w-segments.
// Diagonal skew makes stride-ps smem reads conflict-free (ps+1 odd).
// ============================================================================
__global__ __launch_bounds__(512) void pool_kernel(float* __restrict__ out) {
    const int gz = blockIdx.z;
    const int g  = gz / GF;
    const int f  = gz - g * GF;
    const int b  = blockIdx.y;
    const int p0 = blockIdx.x * PT;

    const int ps  = d_ps[g];
    const int ws  = d_ws[g];
    const int L   = d_L[g];
    const int wsh = ws >> 1;

    extern __shared__ float sm[];
    float* es   = sm + ES_OFF;     // staged energy span
    float* wins = sm + WIN_OFF;    // [ws]
    float* part = sm + PART_OFF;   // [PSUB][PT]

    const int tid = threadIdx.x;
    const int jstart = p0 * ps - wsh;
    const int span   = (PT - 1) * ps + ws;

    const float* ef = d_energy + d_ebase[g] + (f * NBATCH + b) * L;
    for (int i = tid; i < span; i += 512) {
        const int j = jstart + i;
        es[i] = ((unsigned)j < (unsigned)L) ? __ldg(ef + j) : 0.f;
    }
    for (int i = tid; i < ws; i += 512)
        wins[i] = d_win[g][f][i];
    __syncthreads();

    const int pl  = tid & (PT - 1);
    const int sub = tid >> 6;

    const int ws8   = (ws + PSUB - 1) / PSUB;
    const int wbase = sub * ws8;
    int wlen = ws - wbase;
    if (wlen > ws8) wlen = ws8;

    float a = 0.f;
    if (wlen > 0) {
        const float* ep = es + pl * ps;
        const int off = pl % wlen;
        const int wend = wbase + wlen;
        int w = wbase + off;
        #pragma unroll 1
        for (int i = 0; i < wlen; i++) {
            a = fmaf(wins[w], ep[w], a);
            w++;
            if (w >= wend) w -= wlen;
        }
    }
    part[sub * PT + pl] = a;
    __syncthreads();

    if (tid < PT) {
        float s = 0.f;
        #pragma unroll
        for (int k2 = 0; k2 < PSUB; k2++)
            s += part[k2 * PT + tid];
        const int p = p0 + tid;
        if (p < NP)
            out[(b * NP + p) * NF + g * GF + f] = s;
    }
}

// ============================================================================
extern "C" void kernel_launch(void* const* d_in, const int* in_sizes, int n_in,
                              void* d_out, int out_size) {
    const float* x  = (const float*)d_in[0];  // (32, 64000, 1) f32
    const float* cf = (const float*)d_in[1];  // (40,) f32
    const float* bw = (const float*)d_in[2];  // (40,) f32
    const float* pw = (const float*)d_in[3];  // (40,) f32
    float* out = (float*)d_out;               // (32, 400, 40) f32

    cudaFuncSetAttribute(conv_kernel, cudaFuncAttributeMaxDynamicSharedMemorySize, CONV_SMEM);
    cudaFuncSetAttribute(pool_kernel, cudaFuncAttributeMaxDynamicSharedMemorySize, POOL_SMEM);

    setup_meta<<<1, 32>>>(cf, bw);
    setup_weights<<<dim3(8, NG), 256>>>(cf, bw, pw);

    conv_kernel<<<dim3(125, NBATCH, NG), 256, CONV_SMEM>>>(x);

    // Pool: ceil(400/64) = 7 p-tiles, 40 (g,f) planes.
    pool_kernel<<<dim3((NP + PT - 1) / PT, NBATCH, NG * GF), 512, POOL_SMEM>>>(out);
}